// round 1
// baseline (speedup 1.0000x reference)
#include <cuda_runtime.h>

// DistMult edge scoring:
//   out[e] = sum_d X[src[e],d] * R[rel[e],d] * X[dst[e],d],  d in [0,64)
//
// Strategy: 16 threads per edge, one float4 per lane per row.
// Each 16-lane group reads exactly 2 contiguous 128B lines per gathered row
// (perfect sector utilization on the random gathers), then reduces with
// 4 shfl_down steps inside the group. Groups within a warp handle adjacent
// edges, so index loads are broadcast and the scalar output writes from
// lanes 0 and 16 land on adjacent addresses.

constexpr int XDIM = 64;
constexpr int THREADS_PER_EDGE = 16;   // XDIM / 4 floats per lane
constexpr int BLOCK = 256;

__global__ __launch_bounds__(BLOCK)
void distmult_kernel(const float* __restrict__ X,
                     const float* __restrict__ R,
                     const int*   __restrict__ edge_list,  // [2, E] row-major
                     const int*   __restrict__ edge_type,  // [1, E]
                     float*       __restrict__ out,        // [E]
                     int num_edges)
{
    int gid  = blockIdx.x * BLOCK + threadIdx.x;
    int e    = gid >> 4;        // edge index
    int lane = gid & 15;        // 0..15 within the edge group

    bool valid = (e < num_edges);
    int ec = valid ? e : 0;     // clamp so every lane does safe work (shuffle-safe)

    // Broadcast index loads (same address across the 16-lane group -> L1 broadcast)
    int src = __ldg(&edge_list[ec]);
    int dst = __ldg(&edge_list[num_edges + ec]);
    int rel = __ldg(&edge_type[ec]);

    const float4* xs_p = reinterpret_cast<const float4*>(X + (size_t)src * XDIM);
    const float4* xt_p = reinterpret_cast<const float4*>(X + (size_t)dst * XDIM);
    const float4* r_p  = reinterpret_cast<const float4*>(R + (size_t)rel * XDIM);

    // Three independent 16B loads -> good MLP; all three issued before use.
    float4 a = __ldg(xs_p + lane);
    float4 b = __ldg(xt_p + lane);
    float4 r = __ldg(r_p  + lane);

    float s = a.x * r.x * b.x
            + a.y * r.y * b.y
            + a.z * r.z * b.z
            + a.w * r.w * b.w;

    // Reduce across the 16-lane group (all 32 lanes of the warp participate,
    // widths are sub-warp so full mask is safe; tail is handled by clamping).
    #pragma unroll
    for (int off = 8; off > 0; off >>= 1)
        s += __shfl_down_sync(0xFFFFFFFFu, s, off, THREADS_PER_EDGE);

    if (valid && lane == 0)
        out[e] = s;
}

extern "C" void kernel_launch(void* const* d_in, const int* in_sizes, int n_in,
                              void* d_out, int out_size)
{
    const float* X  = (const float*)d_in[0];   // [100000, 64] fp32
    const float* R  = (const float*)d_in[1];   // [237, 64] fp32
    const int* edge_list = (const int*)d_in[2]; // [2, E] int32
    const int* edge_type = (const int*)d_in[3]; // [1, E] int32
    float* out = (float*)d_out;

    int num_edges = in_sizes[3];               // E from edge_type element count

    long long total_threads = (long long)num_edges * THREADS_PER_EDGE;
    int grid = (int)((total_threads + BLOCK - 1) / BLOCK);

    distmult_kernel<<<grid, BLOCK>>>(X, R, edge_list, edge_type, out, num_edges);
}

// round 3
// speedup vs baseline: 1.1469x; 1.1469x over previous
#include <cuda_runtime.h>

// DistMult edge scoring: out[e] = sum_d X[src[e],d] * R[rel[e],d] * X[dst[e],d]
//
// Round 2 (resubmit after infra failure): 16 lanes per group, 2 edges per
// group -> 6 independent LDG.128 in flight per thread (96B MLP) before any
// dependent math. Same perfect 2-lines-per-gathered-row sectoring as round 1,
// half the per-edge index / reduction overhead, paired adjacent stores.

constexpr int XDIM            = 64;
constexpr int LANES           = 16;   // XDIM / 4 floats
constexpr int EDGES_PER_GROUP = 2;
constexpr int BLOCK           = 256;

__global__ __launch_bounds__(BLOCK)
void distmult_kernel(const float* __restrict__ X,
                     const float* __restrict__ R,
                     const int*   __restrict__ edge_list,  // [2, E]
                     const int*   __restrict__ edge_type,  // [1, E]
                     float*       __restrict__ out,        // [E]
                     int num_edges)
{
    int gid   = blockIdx.x * BLOCK + threadIdx.x;
    int group = gid >> 4;
    int lane  = gid & (LANES - 1);

    int e0 = group * EDGES_PER_GROUP;
    int e1 = e0 + 1;
    bool v0 = (e0 < num_edges);
    bool v1 = (e1 < num_edges);
    int e0c = v0 ? e0 : 0;
    int e1c = v1 ? e1 : 0;

    // Index loads: broadcast within each 16-lane group.
    int src0 = __ldg(&edge_list[e0c]);
    int src1 = __ldg(&edge_list[e1c]);
    int dst0 = __ldg(&edge_list[num_edges + e0c]);
    int dst1 = __ldg(&edge_list[num_edges + e1c]);
    int rel0 = __ldg(&edge_type[e0c]);
    int rel1 = __ldg(&edge_type[e1c]);

    const float4* X4 = reinterpret_cast<const float4*>(X);
    const float4* R4 = reinterpret_cast<const float4*>(R);
    const int V4 = XDIM / 4;  // 16 float4 per row

    // Six independent 16B loads -> issued back-to-back, all in flight together.
    float4 a0 = __ldg(X4 + src0 * V4 + lane);
    float4 a1 = __ldg(X4 + src1 * V4 + lane);
    float4 b0 = __ldg(X4 + dst0 * V4 + lane);
    float4 b1 = __ldg(X4 + dst1 * V4 + lane);
    float4 r0 = __ldg(R4 + rel0 * V4 + lane);
    float4 r1 = __ldg(R4 + rel1 * V4 + lane);

    float s0 = a0.x * r0.x * b0.x
             + a0.y * r0.y * b0.y
             + a0.z * r0.z * b0.z
             + a0.w * r0.w * b0.w;
    float s1 = a1.x * r1.x * b1.x
             + a1.y * r1.y * b1.y
             + a1.z * r1.z * b1.z
             + a1.w * r1.w * b1.w;

    // Two interleaved 16-lane reductions (ILP=2 hides SHFL latency).
    #pragma unroll
    for (int off = 8; off > 0; off >>= 1) {
        s0 += __shfl_down_sync(0xFFFFFFFFu, s0, off, LANES);
        s1 += __shfl_down_sync(0xFFFFFFFFu, s1, off, LANES);
    }

    if (lane == 0) {
        if (v0 && v1) {
            // Common case: both edges valid, two adjacent stores.
            out[e0] = s0;
            out[e1] = s1;
        } else {
            if (v0) out[e0] = s0;
            if (v1) out[e1] = s1;
        }
    }
}

extern "C" void kernel_launch(void* const* d_in, const int* in_sizes, int n_in,
                              void* d_out, int out_size)
{
    const float* X  = (const float*)d_in[0];
    const float* R  = (const float*)d_in[1];
    const int* edge_list = (const int*)d_in[2];
    const int* edge_type = (const int*)d_in[3];
    float* out = (float*)d_out;

    int num_edges = in_sizes[3];

    int groups = (num_edges + EDGES_PER_GROUP - 1) / EDGES_PER_GROUP;
    long long total_threads = (long long)groups * LANES;
    int grid = (int)((total_threads + BLOCK - 1) / BLOCK);

    distmult_kernel<<<grid, BLOCK>>>(X, R, edge_list, edge_type, out, num_edges);
}

// round 4
// speedup vs baseline: 1.2006x; 1.0469x over previous
#include <cuda_runtime.h>

// DistMult edge scoring: out[e] = sum_d X[src[e],d] * R[rel[e],d] * X[dst[e],d]
//
// Round 4: 16 lanes/group, 4 edges/group.
//  - int4 index loads (1 LDG.128 per 4 srcs/dsts/rels, broadcast in group)
//  - two-wave gathers (6 LDG.128 in flight per wave) to cap register pressure
//  - folded cross-edge reduction: 8 SHFLs per 4 edges (2/edge, was 4/edge)
//  - results land on lanes 0,8,4,12 -> 4 contiguous scalar stores per group

constexpr int XDIM            = 64;
constexpr int LANES           = 16;
constexpr int EDGES_PER_GROUP = 4;
constexpr int BLOCK           = 256;

__device__ __forceinline__ float dot3(float4 a, float4 r, float4 b) {
    return a.x * r.x * b.x
         + a.y * r.y * b.y
         + a.z * r.z * b.z
         + a.w * r.w * b.w;
}

__global__ __launch_bounds__(BLOCK)
void distmult_kernel(const float* __restrict__ X,
                     const float* __restrict__ R,
                     const int*   __restrict__ edge_list,  // [2, E]
                     const int*   __restrict__ edge_type,  // [1, E]
                     float*       __restrict__ out,        // [E]
                     int num_edges)
{
    int gid   = blockIdx.x * BLOCK + threadIdx.x;
    int group = gid >> 4;
    int lane  = gid & (LANES - 1);

    int e0 = group * EDGES_PER_GROUP;

    int4 src, dst, rel;
    if (e0 + 3 < num_edges) {
        // Fast path (always taken when E % 4 == 0): vectorized index loads.
        src = __ldg(reinterpret_cast<const int4*>(edge_list + e0));
        dst = __ldg(reinterpret_cast<const int4*>(edge_list + num_edges + e0));
        rel = __ldg(reinterpret_cast<const int4*>(edge_type + e0));
    } else {
        int c0 = min(e0 + 0, num_edges - 1);
        int c1 = min(e0 + 1, num_edges - 1);
        int c2 = min(e0 + 2, num_edges - 1);
        int c3 = min(e0 + 3, num_edges - 1);
        src = make_int4(__ldg(&edge_list[c0]), __ldg(&edge_list[c1]),
                        __ldg(&edge_list[c2]), __ldg(&edge_list[c3]));
        dst = make_int4(__ldg(&edge_list[num_edges + c0]), __ldg(&edge_list[num_edges + c1]),
                        __ldg(&edge_list[num_edges + c2]), __ldg(&edge_list[num_edges + c3]));
        rel = make_int4(__ldg(&edge_type[c0]), __ldg(&edge_type[c1]),
                        __ldg(&edge_type[c2]), __ldg(&edge_type[c3]));
    }

    const float4* X4 = reinterpret_cast<const float4*>(X);
    const float4* R4 = reinterpret_cast<const float4*>(R);
    const int V4 = XDIM / 4;  // 16 float4 per row

    // Wave 1: edges 0,1 (6 independent LDG.128 in flight)
    float4 a0 = __ldg(X4 + src.x * V4 + lane);
    float4 b0 = __ldg(X4 + dst.x * V4 + lane);
    float4 r0 = __ldg(R4 + rel.x * V4 + lane);
    float4 a1 = __ldg(X4 + src.y * V4 + lane);
    float4 b1 = __ldg(X4 + dst.y * V4 + lane);
    float4 r1 = __ldg(R4 + rel.y * V4 + lane);
    float s0 = dot3(a0, r0, b0);
    float s1 = dot3(a1, r1, b1);

    // Wave 2: edges 2,3
    float4 a2 = __ldg(X4 + src.z * V4 + lane);
    float4 b2 = __ldg(X4 + dst.z * V4 + lane);
    float4 r2 = __ldg(R4 + rel.z * V4 + lane);
    float4 a3 = __ldg(X4 + src.w * V4 + lane);
    float4 b3 = __ldg(X4 + dst.w * V4 + lane);
    float4 r3 = __ldg(R4 + rel.w * V4 + lane);
    float s2 = dot3(a2, r2, b2);
    float s3 = dot3(a3, r3, b3);

    // Folded reduction: 8 SHFLs for 4 edges.
    // Step 1: fold each at offset 8 (within 16-lane group).
    s0 += __shfl_xor_sync(0xFFFFFFFFu, s0, 8);
    s1 += __shfl_xor_sync(0xFFFFFFFFu, s1, 8);
    s2 += __shfl_xor_sync(0xFFFFFFFFu, s2, 8);
    s3 += __shfl_xor_sync(0xFFFFFFFFu, s3, 8);
    // Halves now each hold 8-lane partial sums; pack two edges per half.
    float a = (lane & 8) ? s1 : s0;   // edge0 in lanes 0-7, edge1 in lanes 8-15
    float b = (lane & 8) ? s3 : s2;   // edge2 in lanes 0-7, edge3 in lanes 8-15
    // Step 2: fold at offset 4, pack again.
    a += __shfl_xor_sync(0xFFFFFFFFu, a, 4);
    b += __shfl_xor_sync(0xFFFFFFFFu, b, 4);
    float c = (lane & 4) ? b : a;
    // quads: lanes0-3 -> edge0, 4-7 -> edge2, 8-11 -> edge1, 12-15 -> edge3
    // Step 3: fold at offsets 2, 1.
    c += __shfl_xor_sync(0xFFFFFFFFu, c, 2);
    c += __shfl_xor_sync(0xFFFFFFFFu, c, 1);

    // Lane base of each quad holds a finished edge:
    // lane0 -> e0+0, lane4 -> e0+2, lane8 -> e0+1, lane12 -> e0+3
    if ((lane & 3) == 0) {
        int off = ((lane >> 3) & 1) | (((lane >> 2) & 1) << 1);
        int e = e0 + off;
        if (e < num_edges)
            out[e] = c;
    }
}

extern "C" void kernel_launch(void* const* d_in, const int* in_sizes, int n_in,
                              void* d_out, int out_size)
{
    const float* X  = (const float*)d_in[0];
    const float* R  = (const float*)d_in[1];
    const int* edge_list = (const int*)d_in[2];
    const int* edge_type = (const int*)d_in[3];
    float* out = (float*)d_out;

    int num_edges = in_sizes[3];

    int groups = (num_edges + EDGES_PER_GROUP - 1) / EDGES_PER_GROUP;
    long long total_threads = (long long)groups * LANES;
    int grid = (int)((total_threads + BLOCK - 1) / BLOCK);

    distmult_kernel<<<grid, BLOCK>>>(X, R, edge_list, edge_type, out, num_edges);
}